// round 4
// baseline (speedup 1.0000x reference)
#include <cuda_runtime.h>
#include <cuda.h>
#include <cuda_bf16.h>
#include <stdint.h>

// ---------------- problem constants ----------------
#define NB   32
#define CIN  256
#define COUT 256
#define H    56
#define W    56
#define HW   (H*W)              // 3136
#define NHW  (NB*HW)            // 100352
#define TAPS 9

// padded pixel space: [n][58][64], pixel p = (n*58 + hh)*64 + ww, valid hh,ww in 1..56
#define PH    58
#define PW    64
#define PPN   (PH*PW)           // 3712
#define PPIX  (NB*PPN)          // 118784
#define GUARD 128
#define MTILE 128
#define NTILES (PPIX / MTILE)   // 928
#define STAGES (TAPS * 2)       // 9 taps x 2 cin-chunks of 128B

#define I8_P1 0x01
#define I8_M1 0xFF

// ---------------- device scratch ----------------
__device__ unsigned char g_xi8[(size_t)(PPIX + 2*GUARD) * 256];   // padded int8 acts (~30.5MB)
__device__ unsigned char g_wi8[TAPS * COUT * CIN];                // int8 weights [tap][oc][cin]
__device__ short         g_y[(size_t)NHW * COUT];                 // conv NHWC int16 (51MB)
__device__ int                g_sum[COUT];
__device__ unsigned long long g_sq[COUT];
__device__ float    g_scale[COUT];
__device__ float    g_shift[COUT];

// ---------------- helpers ----------------
__device__ __forceinline__ uint32_t smem_u32(const void* p) {
    uint32_t a;
    asm("{ .reg .u64 t; cvta.to.shared.u64 t, %1; cvt.u32.u64 %0, t; }" : "=r"(a) : "l"(p));
    return a;
}
#define SWZ128(b) ((b) ^ (((b) >> 3) & 0x70))

__device__ __forceinline__ void cp_async16(uint32_t dst, const void* src) {
    asm volatile("cp.async.ca.shared.global [%0], [%1], 16;" :: "r"(dst), "l"(src));
}
__device__ __forceinline__ void cp_commit() { asm volatile("cp.async.commit_group;"); }
__device__ __forceinline__ void cp_wait1()  { asm volatile("cp.async.wait_group 1;"); }
__device__ __forceinline__ void cp_wait0()  { asm volatile("cp.async.wait_group 0;"); }

__device__ __forceinline__ void ldsm_x4(uint32_t& r0, uint32_t& r1, uint32_t& r2, uint32_t& r3,
                                        uint32_t addr) {
    asm volatile("ldmatrix.sync.aligned.m8n8.x4.shared.b16 {%0,%1,%2,%3}, [%4];"
                 : "=r"(r0), "=r"(r1), "=r"(r2), "=r"(r3) : "r"(addr));
}
__device__ __forceinline__ void imma16832(int* c, const uint32_t* a, const uint32_t* b) {
    asm volatile("mma.sync.aligned.m16n8k32.row.col.s32.s8.s8.s32 "
                 "{%0,%1,%2,%3}, {%4,%5,%6,%7}, {%8,%9}, {%0,%1,%2,%3};"
                 : "+r"(c[0]), "+r"(c[1]), "+r"(c[2]), "+r"(c[3])
                 : "r"(a[0]), "r"(a[1]), "r"(a[2]), "r"(a[3]), "r"(b[0]), "r"(b[1]));
}

// ---------------- kernel 0: zero padded activation buffer ----------------
__global__ void zeroP_kernel() {
    size_t total = ((size_t)(PPIX + 2*GUARD) * 256) / 16;
    uint4 z = make_uint4(0, 0, 0, 0);
    for (size_t i = (size_t)blockIdx.x * blockDim.x + threadIdx.x; i < total;
         i += (size_t)gridDim.x * blockDim.x)
        reinterpret_cast<uint4*>(g_xi8)[i] = z;
}

// ---------------- kernel 1: pack x -> int8 padded [n][58][64][256] ----------------
__global__ void pack_x_kernel(const float* __restrict__ x) {
    __shared__ uint32_t s8[W * 64];
    const int h = blockIdx.x, n = blockIdx.y;
    const int c = threadIdx.x;

    const float4* xp = reinterpret_cast<const float4*>(
        x + ((size_t)(n * CIN + c) * HW) + h * W);
    unsigned char* s8b = reinterpret_cast<unsigned char*>(s8);
#pragma unroll
    for (int wq = 0; wq < 14; wq++) {
        float4 v = __ldg(xp + wq);
        int w0 = wq * 4;
        s8b[(w0 + 0) * 256 + c] = v.x > 0.f ? I8_P1 : I8_M1;
        s8b[(w0 + 1) * 256 + c] = v.y > 0.f ? I8_P1 : I8_M1;
        s8b[(w0 + 2) * 256 + c] = v.z > 0.f ? I8_P1 : I8_M1;
        s8b[(w0 + 3) * 256 + c] = v.w > 0.f ? I8_P1 : I8_M1;
    }
    __syncthreads();

    unsigned char* Pv = g_xi8 + (size_t)GUARD * 256;
    for (int u = threadIdx.x; u < W * 64; u += 256) {
        int wcol = u >> 6;
        int c4   = u & 63;
        size_t dst = (((size_t)(n * PH + h + 1)) * PW + (wcol + 1)) * 256 + c4 * 4;
        *reinterpret_cast<uint32_t*>(Pv + dst) = s8[u];
    }
}

// ---------------- kernel 2: pack w -> int8 [tap][oc][cin], zero stats ----------------
__global__ void pack_w_kernel(const float* __restrict__ w) {
    int tid = blockIdx.x * blockDim.x + threadIdx.x;
    if (tid < COUT) { g_sum[tid] = 0; g_sq[tid] = 0ull; }
    if (tid >= TAPS * COUT * 64) return;
    int t   = tid / 16384;
    int rem = tid - t * 16384;
    int oc  = rem >> 6;
    int c4  = (rem & 63) * 4;
    uint32_t out = 0;
#pragma unroll
    for (int j = 0; j < 4; j++) {
        float v = w[((size_t)oc * CIN + c4 + j) * TAPS + t];
        out |= (uint32_t)(v > 0.f ? I8_P1 : I8_M1) << (8 * j);
    }
    reinterpret_cast<uint32_t*>(g_wi8)[tid] = out;
}

// ---------------- kernel 3: int8 implicit-GEMM conv (mma.sync IMMA) ----------------
// CTA: 128 pixels x 128 oc. 8 warps in 2(M) x 4(N); warp tile 64x32.
// smem: A[2][128x128B] @ 0, B[2][128x128B] @ 32768. 64KB dynamic.
__global__ void __launch_bounds__(256) conv_imma_kernel() {
    extern __shared__ __align__(128) char dsm[];
    const uint32_t sb = smem_u32(dsm);

    const int tid    = threadIdx.x;
    const int lane   = tid & 31;
    const int wid    = tid >> 5;
    const int warp_m = wid >> 2;        // 0..1
    const int warp_n = wid & 3;         // 0..3
    const int gid    = lane >> 2;       // 0..7
    const int qid    = lane & 3;        // 0..3

    const int b0     = blockIdx.x * MTILE;
    const int ocbase = blockIdx.y * 128;

    const unsigned char* Pv = g_xi8 + (size_t)GUARD * 256;

    int c[4][4][4];
#pragma unroll
    for (int mt = 0; mt < 4; mt++)
#pragma unroll
        for (int nt = 0; nt < 4; nt++)
#pragma unroll
            for (int i = 0; i < 4; i++) c[mt][nt][i] = 0;

    // ---- stage issuer (cp.async) ----
    auto issue_stage = [&](int s) {
        const int buf   = s & 1;
        const int tap   = s >> 1;
        const int chunk = s & 1;
        const int shift = (tap / 3 - 1) * PW + (tap % 3 - 1);
        const unsigned char* asrc = Pv + (long long)(b0 + shift) * 256 + chunk * 128;
        const unsigned char* bsrc = g_wi8 + (size_t)tap * 65536 + (size_t)ocbase * 256 + chunk * 128;
        const uint32_t Ab = sb + buf * 16384;
        const uint32_t Bb = sb + 32768 + buf * 16384;
#pragma unroll
        for (int j = 0; j < 4; j++) {               // A: 1024 16B units
            int u = tid + j * 256;
            int r = u >> 3, c16 = u & 7;
            cp_async16(Ab + SWZ128(r * 128 + c16 * 16),
                       asrc + (long long)r * 256 + c16 * 16);
        }
#pragma unroll
        for (int j = 0; j < 4; j++) {               // B: 1024 16B units
            int u = tid + j * 256;
            int r = u >> 3, c16 = u & 7;
            cp_async16(Bb + SWZ128(r * 128 + c16 * 16),
                       bsrc + (size_t)r * 256 + c16 * 16);
        }
        cp_commit();
    };

    issue_stage(0);

    for (int s = 0; s < STAGES; s++) {
        if (s + 1 < STAGES) { issue_stage(s + 1); cp_wait1(); }
        else                { cp_wait0(); }
        __syncthreads();

        const int buf = s & 1;
        const uint32_t Ab = sb + buf * 16384;
        const uint32_t Bb = sb + 32768 + buf * 16384;

#pragma unroll
        for (int ks = 0; ks < 4; ks++) {
            // B fragments: 2x ldmatrix.x4 cover 4 n-tiles
            uint32_t bf[4][2];
#pragma unroll
            for (int half = 0; half < 2; half++) {
                int bn0 = warp_n * 32 + half * 16;
                int i   = lane >> 3, r = lane & 7;
                int row = bn0 + ((i >= 2) ? 8 : 0) + r;
                int off = ks * 32 + (i & 1) * 16;
                uint32_t addr = Bb + SWZ128(row * 128 + off);
                ldsm_x4(bf[half*2][0], bf[half*2][1], bf[half*2+1][0], bf[half*2+1][1], addr);
            }
            // A fragments: 4x ldmatrix.x4 (one per m-tile)
            uint32_t af[4][4];
#pragma unroll
            for (int mt = 0; mt < 4; mt++) {
                int abase = warp_m * 64 + mt * 16;
                int i = lane >> 3, r = lane & 7;
                int row = abase + ((i & 1) ? 8 : 0) + r;
                int off = ks * 32 + ((i >= 2) ? 16 : 0);
                uint32_t addr = Ab + SWZ128(row * 128 + off);
                ldsm_x4(af[mt][0], af[mt][1], af[mt][2], af[mt][3], addr);
            }
#pragma unroll
            for (int mt = 0; mt < 4; mt++)
#pragma unroll
                for (int nt = 0; nt < 4; nt++)
                    imma16832(c[mt][nt], af[mt], bf[nt]);
        }
        __syncthreads();
    }

    // ---- epilogue: store y NHWC + exact integer stats ----
    int sAcc[8], qAcc[8];
#pragma unroll
    for (int k = 0; k < 8; k++) { sAcc[k] = 0; qAcc[k] = 0; }

#pragma unroll
    for (int mt = 0; mt < 4; mt++) {
#pragma unroll
        for (int half = 0; half < 2; half++) {
            int pl = warp_m * 64 + mt * 16 + gid + half * 8;
            int p  = b0 + pl;
            int n   = p / PPN;
            int rem = p - n * PPN;
            int rr  = rem >> 6;
            int cc  = rem & 63;
            if (rr >= 1 && rr <= H && cc >= 1 && cc <= W) {
                size_t ybase = (((size_t)n * H + (rr - 1)) * W + (cc - 1)) * COUT + ocbase;
#pragma unroll
                for (int nt = 0; nt < 4; nt++) {
                    int v0 = c[mt][nt][half * 2 + 0];
                    int v1 = c[mt][nt][half * 2 + 1];
                    int ocl = warp_n * 32 + nt * 8 + qid * 2;
                    short2 sv;
                    sv.x = (short)v0; sv.y = (short)v1;
                    *reinterpret_cast<short2*>(&g_y[ybase + ocl]) = sv;
                    sAcc[nt * 2]     += v0;
                    sAcc[nt * 2 + 1] += v1;
                    qAcc[nt * 2]     += v0 * v0;
                    qAcc[nt * 2 + 1] += v1 * v1;
                }
            }
        }
    }

    __syncthreads();                                 // smem free now
    int* sstat = reinterpret_cast<int*>(dsm);        // [0..127] sum, [128..255] sq
    sstat[tid] = 0;
    __syncthreads();
#pragma unroll
    for (int k = 0; k < 8; k++) {
        int ocl = warp_n * 32 + (k >> 1) * 8 + qid * 2 + (k & 1);
        atomicAdd(&sstat[ocl], sAcc[k]);
        atomicAdd(&sstat[128 + ocl], qAcc[k]);
    }
    __syncthreads();
    if (tid < 128) {
        atomicAdd(&g_sum[ocbase + tid], sstat[tid]);
        atomicAdd(&g_sq[ocbase + tid], (unsigned long long)(long long)sstat[128 + tid]);
    }
}

// ---------------- kernel 4: BN scale/shift ----------------
__global__ void stats_kernel(const float* __restrict__ gamma,
                             const float* __restrict__ beta) {
    int c = threadIdx.x;
    const double cnt = (double)NHW;
    double mean = (double)g_sum[c] / cnt;
    double ex2  = (double)(long long)g_sq[c] / cnt;
    double var  = ex2 - mean * mean;
    double inv  = 1.0 / sqrt(var + 1e-5);
    double sc   = (double)gamma[c] * inv;
    g_scale[c] = (float)sc;
    g_shift[c] = (float)((double)beta[c] - mean * sc);
}

// ---------------- kernel 5: BN apply + NHWC -> NCHW ----------------
#define WT 28
__global__ void __launch_bounds__(256)
apply_kernel(float* __restrict__ out) {
    __shared__ float sy[WT * 257];
    const int wt = blockIdx.x, h = blockIdx.y, n = blockIdx.z;
    const int tid = threadIdx.x;

    for (int idx = tid; idx < WT * COUT; idx += 256) {
        int lw = idx >> 8;
        int oc = idx & 255;
        int gw = wt * WT + lw;
        float yv = (float)g_y[(((size_t)n * H + h) * W + gw) * COUT + oc];
        sy[lw * 257 + oc] = yv * g_scale[oc] + g_shift[oc];
    }
    __syncthreads();
    for (int idx = tid; idx < WT * COUT; idx += 256) {
        int oc = idx / WT;
        int lw = idx - oc * WT;
        out[(((size_t)n * COUT + oc) * H + h) * W + wt * WT + lw] = sy[lw * 257 + oc];
    }
}

// ---------------- launch ----------------
extern "C" void kernel_launch(void* const* d_in, const int* in_sizes, int n_in,
                              void* d_out, int out_size) {
    const float* x     = (const float*)d_in[0];
    const float* w     = (const float*)d_in[1];
    const float* gamma = (const float*)d_in[2];
    const float* beta  = (const float*)d_in[3];
    float* out = (float*)d_out;

    cudaFuncSetAttribute(conv_imma_kernel,
                         cudaFuncAttributeMaxDynamicSharedMemorySize, 65536);

    zeroP_kernel<<<2048, 256>>>();
    pack_x_kernel<<<dim3(H, NB), 256>>>(x);
    pack_w_kernel<<<(TAPS * COUT * 64 + 255) / 256, 256>>>(w);
    conv_imma_kernel<<<dim3(NTILES, 2), 256, 65536>>>();
    stats_kernel<<<1, COUT>>>(gamma, beta);
    apply_kernel<<<dim3(W / WT, H, NB), 256>>>(out);
}

// round 5
// speedup vs baseline: 1.9886x; 1.9886x over previous
#include <cuda_runtime.h>
#include <cuda.h>
#include <cuda_bf16.h>
#include <stdint.h>

// ---------------- problem constants ----------------
#define NB   32
#define CIN  256
#define COUT 256
#define H    56
#define W    56
#define HW   (H*W)              // 3136
#define NHW  (NB*HW)            // 100352
#define TAPS 9
#define CW   8                  // 256 bits = 8 u32 words

// padded pixel space for IMMA: [n][58][64]
#define PH    58
#define PW    64
#define PPN   (PH*PW)           // 3712
#define PPIX  (NB*PPN)          // 118784
#define GUARD 128
#define MTILE 128

// hybrid split: batches [0,NBP) -> POPC path, [NBP,NB) -> IMMA path
#define NBP   21
#define TH    4                                    // POPC rows per CTA
#define VPOP  (NBP*HW)                             // 65856 valid pixels (POPC)
#define VIM   (NHW - VPOP)                         // 34496 valid pixels (IMMA)
#define ITILES ((VIM + MTILE - 1)/MTILE)           // 270
#define IMMA_CTAS (ITILES*2)                       // 540 (x2 oc halves)
#define POPC_CTAS (NBP*(H/TH))                     // 294
#define GRID_TOT  (POPC_CTAS + IMMA_CTAS)          // 834
#define STAGES (TAPS * 2)

#define I8_P1 0x01
#define I8_M1 0xFF

// smem layout for IMMA path inside dynamic smem
#define SMEM_DYN  66048          // A[2]*16K + B[2]*16K + pp table 512B

// ---------------- device scratch ----------------
__device__ uint32_t      g_xb[(size_t)NB*HW*CW];                  // bitpacked acts (POPC)
__device__ unsigned char g_xi8[(size_t)(PPIX + 2*GUARD) * 256];   // padded int8 acts (IMMA)
__device__ uint32_t      g_wb[COUT*TAPS*CW];                      // bit weights [oc][tap][8]
__device__ unsigned char g_wi8[TAPS * COUT * CIN];                // int8 weights [tap][oc][cin]
__device__ short         g_y[(size_t)NHW * COUT];                 // conv NHWC int16
__device__ int                g_sum[COUT];
__device__ unsigned long long g_sq[COUT];
__device__ float    g_scale[COUT];
__device__ float    g_shift[COUT];

// ---------------- helpers ----------------
__device__ __forceinline__ uint32_t smem_u32(const void* p) {
    uint32_t a;
    asm("{ .reg .u64 t; cvta.to.shared.u64 t, %1; cvt.u32.u64 %0, t; }" : "=r"(a) : "l"(p));
    return a;
}
#define SWZ128(b) ((b) ^ (((b) >> 3) & 0x70))

__device__ __forceinline__ void cp_async16(uint32_t dst, const void* src) {
    asm volatile("cp.async.ca.shared.global [%0], [%1], 16;" :: "r"(dst), "l"(src));
}
__device__ __forceinline__ void cp_commit() { asm volatile("cp.async.commit_group;"); }
__device__ __forceinline__ void cp_wait1()  { asm volatile("cp.async.wait_group 1;"); }
__device__ __forceinline__ void cp_wait0()  { asm volatile("cp.async.wait_group 0;"); }

__device__ __forceinline__ void ldsm_x4(uint32_t& r0, uint32_t& r1, uint32_t& r2, uint32_t& r3,
                                        uint32_t addr) {
    asm volatile("ldmatrix.sync.aligned.m8n8.x4.shared.b16 {%0,%1,%2,%3}, [%4];"
                 : "=r"(r0), "=r"(r1), "=r"(r2), "=r"(r3) : "r"(addr));
}
__device__ __forceinline__ void imma16832(int* c, const uint32_t* a, const uint32_t* b) {
    asm volatile("mma.sync.aligned.m16n8k32.row.col.s32.s8.s8.s32 "
                 "{%0,%1,%2,%3}, {%4,%5,%6,%7}, {%8,%9}, {%0,%1,%2,%3};"
                 : "+r"(c[0]), "+r"(c[1]), "+r"(c[2]), "+r"(c[3])
                 : "r"(a[0]), "r"(a[1]), "r"(a[2]), "r"(a[3]), "r"(b[0]), "r"(b[1]));
}

// ---------------- kernel 0: zero padded int8 buffer ----------------
__global__ void zeroP_kernel() {
    size_t total = ((size_t)(PPIX + 2*GUARD) * 256) / 16;
    uint4 z = make_uint4(0, 0, 0, 0);
    for (size_t i = (size_t)blockIdx.x * blockDim.x + threadIdx.x; i < total;
         i += (size_t)gridDim.x * blockDim.x)
        reinterpret_cast<uint4*>(g_xi8)[i] = z;
}

// ---------------- kernel 1: pack x (bitplanes for n<NBP, int8 padded for n>=NBP) ----------------
__global__ void pack_x_kernel(const float* __restrict__ x) {
    __shared__ uint32_t s8[W * 64];                // int8 staged [w][c], 14336B
    const int h = blockIdx.x, n = blockIdx.y;
    const int c = threadIdx.x;

    const float4* xp = reinterpret_cast<const float4*>(
        x + ((size_t)(n * CIN + c) * HW) + h * W);
    unsigned char* s8b = reinterpret_cast<unsigned char*>(s8);
#pragma unroll
    for (int wq = 0; wq < 14; wq++) {
        float4 v = __ldg(xp + wq);
        int w0 = wq * 4;
        s8b[(w0 + 0) * 256 + c] = v.x > 0.f ? I8_P1 : I8_M1;
        s8b[(w0 + 1) * 256 + c] = v.y > 0.f ? I8_P1 : I8_M1;
        s8b[(w0 + 2) * 256 + c] = v.z > 0.f ? I8_P1 : I8_M1;
        s8b[(w0 + 3) * 256 + c] = v.w > 0.f ? I8_P1 : I8_M1;
    }
    __syncthreads();

    if (n >= NBP) {
        // IMMA format: padded [n][58][64][256] int8
        unsigned char* Pv = g_xi8 + (size_t)GUARD * 256;
        for (int u = threadIdx.x; u < W * 64; u += 256) {
            int wcol = u >> 6;
            int c4   = u & 63;
            size_t dst = (((size_t)(n * PH + h + 1)) * PW + (wcol + 1)) * 256 + c4 * 4;
            *reinterpret_cast<uint32_t*>(g_xi8 + (size_t)GUARD * 256 + dst - dst + dst) = s8[u];
            (void)Pv;
        }
    } else {
        // POPC format: bitplanes [n][h][w][8], bit=1 iff x>0 (byte==0x01)
        for (int u = threadIdx.x; u < W * CW; u += 256) {
            int wcol = u >> 3;
            int wd   = u & 7;
            uint32_t bits = 0;
#pragma unroll
            for (int q = 0; q < 8; q++) {
                uint32_t wo  = s8[wcol * 64 + wd * 8 + q];
                uint32_t pos = ~wo & 0x80808080u;          // sign==0 -> positive
                bits |= ((pos >> 7)  & 1u) << (q * 4 + 0);
                bits |= ((pos >> 15) & 1u) << (q * 4 + 1);
                bits |= ((pos >> 23) & 1u) << (q * 4 + 2);
                bits |= ((pos >> 31)      ) << (q * 4 + 3);
            }
            g_xb[(((size_t)n * H + h) * W + wcol) * CW + wd] = bits;
        }
    }
}

// ---------------- kernel 2a: pack bit weights [oc][tap][8] ----------------
__global__ void pack_wb_kernel(const float* __restrict__ w) {
    int tid = blockIdx.x * blockDim.x + threadIdx.x;
    if (tid >= COUT * TAPS * CW) return;
    int oc   = tid / (TAPS * CW);
    int r    = tid - oc * (TAPS * CW);
    int tap  = r >> 3;
    int word = r & 7;
    uint32_t bits = 0u;
#pragma unroll
    for (int j = 0; j < 32; j++) {
        int ci = (word << 5) + j;
        float v = w[(size_t)(oc * CIN + ci) * TAPS + tap];
        bits |= (v > 0.f ? 1u : 0u) << j;
    }
    g_wb[tid] = bits;
}

// ---------------- kernel 2b: pack int8 weights [tap][oc][cin] + zero stats ----------------
__global__ void pack_wi8_kernel(const float* __restrict__ w) {
    int tid = blockIdx.x * blockDim.x + threadIdx.x;
    if (tid < COUT) { g_sum[tid] = 0; g_sq[tid] = 0ull; }
    if (tid >= TAPS * COUT * 64) return;
    int t   = tid / 16384;
    int rem = tid - t * 16384;
    int oc  = rem >> 6;
    int c4  = (rem & 63) * 4;
    uint32_t out = 0;
#pragma unroll
    for (int j = 0; j < 4; j++) {
        float v = w[((size_t)oc * CIN + c4 + j) * TAPS + t];
        out |= (uint32_t)(v > 0.f ? I8_P1 : I8_M1) << (8 * j);
    }
    reinterpret_cast<uint32_t*>(g_wi8)[tid] = out;
}

// ---------------- kernel 3: HYBRID conv (POPC CTAs + IMMA CTAs) ----------------
__global__ void __launch_bounds__(256, 2) conv_hybrid_kernel() {
    extern __shared__ __align__(128) char dsm[];
    __shared__ uint32_t sx[TH + 2][W + 2][CW];         // POPC x-tile (11KB static)

    const int bid = blockIdx.x;
    const int tid = threadIdx.x;

    // ---- role decode: wave-1 pairs 148 POPC + 148 IMMA per SM, rest proportional ----
    int role, id;                                      // role 0 = POPC, 1 = IMMA
    if (bid < 148)      { role = 0; id = bid; }
    else if (bid < 296) { role = 1; id = bid - 148; }
    else {
        int r = bid - 296;                             // 0..537
        int pprev = (r * (POPC_CTAS - 148)) / (GRID_TOT - 296);
        int pcur  = ((r + 1) * (POPC_CTAS - 148)) / (GRID_TOT - 296);
        if (pcur > pprev) { role = 0; id = 148 + pprev; }
        else              { role = 1; id = 148 + (r - pprev); }
    }

    if (role == 0) {
        // ================= POPC path (alu pipe) =================
        const int n   = id / (H / TH);
        const int oh0 = (id - n * (H / TH)) * TH;
        const int oc  = tid;

        const int TOT = (TH + 2) * (W + 2) * CW;
        for (int i = oc; i < TOT; i += 256) {
            int wrd  = i & 7;
            int rest = i >> 3;
            int c    = rest % (W + 2);
            int r    = rest / (W + 2);
            int gh   = oh0 - 1 + r;
            int gw   = c - 1;
            uint32_t v = 0u;
            if (gh >= 0 && gh < H && gw >= 0 && gw < W)
                v = g_xb[(((size_t)n * H + gh) * W + gw) * CW + wrd];
            sx[r][c][wrd] = v;
        }

        uint32_t wr[TAPS][CW];
        int      Ct[TAPS];
        {
            const uint32_t* wp = &g_wb[(size_t)oc * TAPS * CW];
#pragma unroll
            for (int t = 0; t < TAPS; t++) {
                int p = 0;
#pragma unroll
                for (int k = 0; k < CW; k++) {
                    uint32_t v = __ldg(wp + t * CW + k);
                    wr[t][k] = v;
                    p += __popc(v);
                }
                Ct[t] = CIN - 2 * p;
            }
        }
        __syncthreads();

        int       lsum = 0;
        long long lsq  = 0;
        for (int oh = 0; oh < TH; oh++) {
            const int gh = oh0 + oh;
            for (int ow = 0; ow < W; ow++) {
                int s = 0;
#pragma unroll
                for (int t = 0; t < TAPS; t++) {
                    const int r = oh + t / 3;
                    const int c = ow + t % 3;
                    const uint4 xa = *reinterpret_cast<const uint4*>(&sx[r][c][0]);
                    const uint4 xb = *reinterpret_cast<const uint4*>(&sx[r][c][4]);
                    s += __popc(xa.x ^ wr[t][0]);
                    s += __popc(xa.y ^ wr[t][1]);
                    s += __popc(xa.z ^ wr[t][2]);
                    s += __popc(xa.w ^ wr[t][3]);
                    s += __popc(xb.x ^ wr[t][4]);
                    s += __popc(xb.y ^ wr[t][5]);
                    s += __popc(xb.z ^ wr[t][6]);
                    s += __popc(xb.w ^ wr[t][7]);
                }
                int yv = CIN * TAPS - 2 * s;
                int inv = 0;
                if (gh == 0)     inv |= 0x007;
                if (gh == H - 1) inv |= 0x1C0;
                if (ow == 0)     inv |= 0x049;
                if (ow == W - 1) inv |= 0x124;
                if (inv) {
#pragma unroll
                    for (int t = 0; t < TAPS; t++)
                        if ((inv >> t) & 1) yv -= Ct[t];
                }
                g_y[(((size_t)n * H + gh) * W + ow) * COUT + oc] = (short)yv;
                lsum += yv;
                lsq  += (long long)(yv * yv);
            }
        }
        atomicAdd(&g_sum[oc], lsum);
        atomicAdd(&g_sq[oc], (unsigned long long)lsq);
        return;
    }

    // ================= IMMA path (tensor pipe), valid-pixel gathered tiles =================
    const uint32_t sb = smem_u32(dsm);
    const int lane   = tid & 31;
    const int wid    = tid >> 5;
    const int warp_m = wid >> 2;
    const int warp_n = wid & 3;
    const int gid    = lane >> 2;
    const int qid    = lane & 3;

    const int tile   = id >> 1;
    const int ocbase = (id & 1) * 128;
    const unsigned char* Pv = g_xi8 + (size_t)GUARD * 256;

    // row -> padded pixel index table (gathered valid pixels)
    int* pp = reinterpret_cast<int*>(dsm + 65536);
    if (tid < MTILE) {
        int v = tile * MTILE + tid;
        int ppix;
        if (v < VIM) {
            int gv  = VPOP + v;
            int n   = gv / HW;
            int rem = gv - n * HW;
            int h   = rem / W;
            int w   = rem - h * W;
            ppix = (n * PH + h + 1) * PW + (w + 1);
        } else {
            ppix = NBP * PPN;                          // a pad row: guaranteed zero
        }
        pp[tid] = ppix;
    }
    __syncthreads();

    int ppr[4];
    {
        int rbase = tid >> 3;
#pragma unroll
        for (int j = 0; j < 4; j++) ppr[j] = pp[rbase + j * 32];
    }

    int c[4][4][4];
#pragma unroll
    for (int mt = 0; mt < 4; mt++)
#pragma unroll
        for (int nt = 0; nt < 4; nt++)
#pragma unroll
            for (int i = 0; i < 4; i++) c[mt][nt][i] = 0;

    auto issue_stage = [&](int s) {
        const int buf   = s & 1;
        const int tap   = s >> 1;
        const int chunk = s & 1;
        const int shift = (tap / 3 - 1) * PW + (tap % 3 - 1);
        const unsigned char* bsrc = g_wi8 + (size_t)tap * 65536 + (size_t)ocbase * 256 + chunk * 128;
        const uint32_t Ab = sb + buf * 16384;
        const uint32_t Bb = sb + 32768 + buf * 16384;
#pragma unroll
        for (int j = 0; j < 4; j++) {                  // A: gathered rows
            int u = tid + j * 256;
            int r = u >> 3, c16 = u & 7;
            cp_async16(Ab + SWZ128(r * 128 + c16 * 16),
                       Pv + (long long)(ppr[j] + shift) * 256 + chunk * 128 + c16 * 16);
        }
#pragma unroll
        for (int j = 0; j < 4; j++) {                  // B
            int u = tid + j * 256;
            int r = u >> 3, c16 = u & 7;
            cp_async16(Bb + SWZ128(r * 128 + c16 * 16),
                       bsrc + (size_t)r * 256 + c16 * 16);
        }
        cp_commit();
    };

    issue_stage(0);

    for (int s = 0; s < STAGES; s++) {
        if (s + 1 < STAGES) { issue_stage(s + 1); cp_wait1(); }
        else                { cp_wait0(); }
        __syncthreads();

        const int buf = s & 1;
        const uint32_t Ab = sb + buf * 16384;
        const uint32_t Bb = sb + 32768 + buf * 16384;

#pragma unroll
        for (int ks = 0; ks < 4; ks++) {
            uint32_t bf[4][2];
#pragma unroll
            for (int half = 0; half < 2; half++) {
                int bn0 = warp_n * 32 + half * 16;
                int i   = lane >> 3, r = lane & 7;
                int row = bn0 + ((i >= 2) ? 8 : 0) + r;
                int off = ks * 32 + (i & 1) * 16;
                uint32_t addr = Bb + SWZ128(row * 128 + off);
                ldsm_x4(bf[half*2][0], bf[half*2][1], bf[half*2+1][0], bf[half*2+1][1], addr);
            }
            uint32_t af[4][4];
#pragma unroll
            for (int mt = 0; mt < 4; mt++) {
                int abase = warp_m * 64 + mt * 16;
                int i = lane >> 3, r = lane & 7;
                int row = abase + ((i & 1) ? 8 : 0) + r;
                int off = ks * 32 + ((i >= 2) ? 16 : 0);
                uint32_t addr = Ab + SWZ128(row * 128 + off);
                ldsm_x4(af[mt][0], af[mt][1], af[mt][2], af[mt][3], addr);
            }
#pragma unroll
            for (int mt = 0; mt < 4; mt++)
#pragma unroll
                for (int nt = 0; nt < 4; nt++)
                    imma16832(c[mt][nt], af[mt], bf[nt]);
        }
        __syncthreads();
    }

    // ---- epilogue: store y NHWC + exact integer stats ----
    int sAcc[8], qAcc[8];
#pragma unroll
    for (int k = 0; k < 8; k++) { sAcc[k] = 0; qAcc[k] = 0; }

#pragma unroll
    for (int mt = 0; mt < 4; mt++) {
#pragma unroll
        for (int half = 0; half < 2; half++) {
            int pl = warp_m * 64 + mt * 16 + gid + half * 8;
            int v  = tile * MTILE + pl;
            if (v < VIM) {
                size_t gv = (size_t)(VPOP + v);
                size_t ybase = gv * COUT + ocbase;
#pragma unroll
                for (int nt = 0; nt < 4; nt++) {
                    int v0 = c[mt][nt][half * 2 + 0];
                    int v1 = c[mt][nt][half * 2 + 1];
                    int ocl = warp_n * 32 + nt * 8 + qid * 2;
                    short2 sv;
                    sv.x = (short)v0; sv.y = (short)v1;
                    *reinterpret_cast<short2*>(&g_y[ybase + ocl]) = sv;
                    sAcc[nt * 2]     += v0;
                    sAcc[nt * 2 + 1] += v1;
                    qAcc[nt * 2]     += v0 * v0;
                    qAcc[nt * 2 + 1] += v1 * v1;
                }
            }
        }
    }

    __syncthreads();
    int* sstat = reinterpret_cast<int*>(dsm);          // reuse A buffer
    sstat[tid] = 0;
    __syncthreads();
#pragma unroll
    for (int k = 0; k < 8; k++) {
        int ocl = warp_n * 32 + (k >> 1) * 8 + qid * 2 + (k & 1);
        atomicAdd(&sstat[ocl], sAcc[k]);
        atomicAdd(&sstat[128 + ocl], qAcc[k]);
    }
    __syncthreads();
    if (tid < 128) {
        atomicAdd(&g_sum[ocbase + tid], sstat[tid]);
        atomicAdd(&g_sq[ocbase + tid], (unsigned long long)(long long)sstat[128 + tid]);
    }
}

// ---------------- kernel 4: BN scale/shift ----------------
__global__ void stats_kernel(const float* __restrict__ gamma,
                             const float* __restrict__ beta) {
    int c = threadIdx.x;
    const double cnt = (double)NHW;
    double mean = (double)g_sum[c] / cnt;
    double ex2  = (double)(long long)g_sq[c] / cnt;
    double var  = ex2 - mean * mean;
    double inv  = 1.0 / sqrt(var + 1e-5);
    double sc   = (double)gamma[c] * inv;
    g_scale[c] = (float)sc;
    g_shift[c] = (float)((double)beta[c] - mean * sc);
}

// ---------------- kernel 5: BN apply + NHWC -> NCHW ----------------
#define WT 28
__global__ void __launch_bounds__(256)
apply_kernel(float* __restrict__ out) {
    __shared__ float sy[WT * 257];
    const int wt = blockIdx.x, h = blockIdx.y, n = blockIdx.z;
    const int tid = threadIdx.x;

    for (int idx = tid; idx < WT * COUT; idx += 256) {
        int lw = idx >> 8;
        int oc = idx & 255;
        int gw = wt * WT + lw;
        float yv = (float)g_y[(((size_t)n * H + h) * W + gw) * COUT + oc];
        sy[lw * 257 + oc] = yv * g_scale[oc] + g_shift[oc];
    }
    __syncthreads();
    for (int idx = tid; idx < WT * COUT; idx += 256) {
        int oc = idx / WT;
        int lw = idx - oc * WT;
        out[(((size_t)n * COUT + oc) * H + h) * W + wt * WT + lw] = sy[lw * 257 + oc];
    }
}

// ---------------- launch ----------------
extern "C" void kernel_launch(void* const* d_in, const int* in_sizes, int n_in,
                              void* d_out, int out_size) {
    const float* x     = (const float*)d_in[0];
    const float* w     = (const float*)d_in[1];
    const float* gamma = (const float*)d_in[2];
    const float* beta  = (const float*)d_in[3];
    float* out = (float*)d_out;

    cudaFuncSetAttribute(conv_hybrid_kernel,
                         cudaFuncAttributeMaxDynamicSharedMemorySize, SMEM_DYN);

    zeroP_kernel<<<2048, 256>>>();
    pack_x_kernel<<<dim3(H, NB), 256>>>(x);
    pack_wb_kernel<<<(COUT * TAPS * CW + 255) / 256, 256>>>(w);
    pack_wi8_kernel<<<(TAPS * COUT * 64 + 255) / 256, 256>>>(w);
    conv_hybrid_kernel<<<GRID_TOT, 256, SMEM_DYN>>>();
    stats_kernel<<<1, COUT>>>(gamma, beta);
    apply_kernel<<<dim3(W / WT, H, NB), 256>>>(out);
}

// round 7
// speedup vs baseline: 2.7434x; 1.3796x over previous
#include <cuda_runtime.h>
#include <cuda_bf16.h>
#include <stdint.h>

// ---------------- problem constants ----------------
#define NB   32
#define CIN  256
#define COUT 256
#define H    56
#define W    56
#define HW   (H*W)          // 3136
#define NHW  (NB*HW)        // 100352
#define CW   8              // 256 bits = 8 u32 words
#define TAPS 9

// persistent conv grid: 2 CTAs per SM on GB300 (152 SMs)
#define NSM      152
#define CONV_CTAS (2*NSM)   // 304
// item = (n, h, half-row of 28 px): 32*56*2 = 3584 items, 112 per batch
#define WHALF 28
#define IPB   (H*2)         // 112 items per batch
#define NITEMS (NB*IPB)     // 3584

// ---------------- device scratch ----------------
__device__ uint32_t g_xb[(size_t)NB*HW*CW];   // packed activations [n][h][w][8] (3.2 MB)
__device__ uint32_t g_wb[COUT*TAPS*CW];       // packed weights [oc][tap][8] (72 KB)
__device__ short    g_y[(size_t)NHW*COUT];    // conv result NHWC int16 (51 MB)
__device__ int                g_sum[COUT];
__device__ unsigned long long g_sq[COUT];
__device__ float    g_scale[COUT];
__device__ float    g_shift[COUT];

// ---------------- kernel 1: pack activations into bitplanes ----------------
__global__ void pack_x_kernel(const float* __restrict__ x) {
    int tid = blockIdx.x * blockDim.x + threadIdx.x;   // one thread per (n,h,w)
    if (tid >= NHW) return;
    int n   = tid / HW;
    int rem = tid - n * HW;

    uint32_t wds[CW];
#pragma unroll
    for (int i = 0; i < CW; i++) wds[i] = 0u;

#pragma unroll 8
    for (int c = 0; c < CIN; c++) {
        float v = x[(size_t)(n * CIN + c) * HW + rem];
        uint32_t bit = (v > 0.0f) ? 1u : 0u;
        wds[c >> 5] |= bit << (c & 31);
    }
    uint4* dst = reinterpret_cast<uint4*>(&g_xb[(size_t)tid * CW]);
    dst[0] = make_uint4(wds[0], wds[1], wds[2], wds[3]);
    dst[1] = make_uint4(wds[4], wds[5], wds[6], wds[7]);
}

// ---------------- kernel 2: pack weights + zero the stat accumulators ----------------
__global__ void pack_w_kernel(const float* __restrict__ w) {
    int tid = blockIdx.x * blockDim.x + threadIdx.x;   // one thread per (oc,tap,word)
    if (tid < COUT) { g_sum[tid] = 0; g_sq[tid] = 0ull; }
    if (tid >= COUT * TAPS * CW) return;
    int oc   = tid / (TAPS * CW);
    int r    = tid - oc * (TAPS * CW);
    int tap  = r >> 3;
    int word = r & 7;

    uint32_t bits = 0u;
#pragma unroll
    for (int j = 0; j < 32; j++) {
        int ci = (word << 5) + j;
        float v = w[(size_t)(oc * CIN + ci) * TAPS + tap];
        bits |= (v > 0.f ? 1u : 0u) << j;
    }
    g_wb[tid] = bits;
}

// ---------------- kernel 3: persistent XNOR-popcount conv (CSA-compressed) ----------------
// 304 persistent CTAs, items = (n, h, whalf). Thread = output channel.
__global__ void __launch_bounds__(256, 2)
conv_kernel() {
    __shared__ uint32_t sx[3][WHALF + 2][CW];          // 2.9 KB per CTA

    const int oc  = threadIdx.x;

    // per-thread weights (72 regs) + per-tap zero-halo correction Ct
    uint32_t wr[TAPS][CW];
    int      Ct[TAPS];
    {
        const uint32_t* wp = &g_wb[(size_t)oc * TAPS * CW];
#pragma unroll
        for (int t = 0; t < TAPS; t++) {
            int p = 0;
#pragma unroll
            for (int k = 0; k < CW; k++) {
                uint32_t v = __ldg(wp + t * CW + k);
                wr[t][k] = v;
                p += __popc(v);
            }
            Ct[t] = CIN - 2 * p;                       // contribution of a zero-halo tap
        }
    }

    int       lsum = 0;
    long long lsq  = 0;

    for (int item = blockIdx.x; item < NITEMS; item += CONV_CTAS) {
        const int n   = item / IPB;                    // 112 items per batch
        const int r2  = item - n * IPB;                // h*2 + whalf
        const int h   = r2 >> 1;
        const int wh0 = (r2 & 1) * WHALF;

        __syncthreads();                               // protect prior sx reads

        // cooperative load of x bit-tile: rows h-1..h+1, cols wh0-1..wh0+28
        const int TOT = 3 * (WHALF + 2) * CW;          // 720 words
        for (int i = oc; i < TOT; i += 256) {
            int wrd  = i & 7;
            int rest = i >> 3;
            int lc   = rest % (WHALF + 2);
            int r    = rest / (WHALF + 2);
            int gh   = h - 1 + r;
            int gw   = wh0 - 1 + lc;
            uint32_t v = 0u;
            if (gh >= 0 && gh < H && gw >= 0 && gw < W)
                v = g_xb[(((size_t)n * H + gh) * W + gw) * CW + wrd];
            sx[r][lc][wrd] = v;
        }
        __syncthreads();

        short* yrow = &g_y[(((size_t)n * H + h) * W + wh0) * COUT + oc];

        for (int ol = 0; ol < WHALF; ol++) {
            const int ow = wh0 + ol;
            int s1 = 0, s2 = 0;                        // plain / carry(x2) popcounts
#pragma unroll
            for (int g = 0; g < 3; g++) {              // tap rows: taps 3g..3g+2
                const uint4 xa0 = *reinterpret_cast<const uint4*>(&sx[g][ol + 0][0]);
                const uint4 xb0 = *reinterpret_cast<const uint4*>(&sx[g][ol + 0][4]);
                const uint4 xa1 = *reinterpret_cast<const uint4*>(&sx[g][ol + 1][0]);
                const uint4 xb1 = *reinterpret_cast<const uint4*>(&sx[g][ol + 1][4]);
                const uint4 xa2 = *reinterpret_cast<const uint4*>(&sx[g][ol + 2][0]);
                const uint4 xb2 = *reinterpret_cast<const uint4*>(&sx[g][ol + 2][4]);
                uint32_t x0[8] = {xa0.x, xa0.y, xa0.z, xa0.w, xb0.x, xb0.y, xb0.z, xb0.w};
                uint32_t x1[8] = {xa1.x, xa1.y, xa1.z, xa1.w, xb1.x, xb1.y, xb1.z, xb1.w};
                uint32_t x2[8] = {xa2.x, xa2.y, xa2.z, xa2.w, xb2.x, xb2.y, xb2.z, xb2.w};
#pragma unroll
                for (int k = 0; k < CW; k++) {
                    uint32_t a = x0[k] ^ wr[3 * g + 0][k];
                    uint32_t b = x1[k] ^ wr[3 * g + 1][k];
                    uint32_t c = x2[k] ^ wr[3 * g + 2][k];
                    uint32_t sum = a ^ b ^ c;                        // LOP3 0x96
                    uint32_t maj = (a & b) | (a & c) | (b & c);     // LOP3 0xE8
                    s1 += __popc(sum);
                    s2 += __popc(maj);
                }
            }
            int s  = s1 + 2 * s2;                      // exact Σ popc over 72 words
            int yv = CIN * TAPS - 2 * s;               // includes zero-halo taps

            // subtract zero-halo tap contributions
            int inv = 0;
            if (h == 0)      inv |= 0x007;             // taps 0,1,2
            if (h == H - 1)  inv |= 0x1C0;             // taps 6,7,8
            if (ow == 0)     inv |= 0x049;             // taps 0,3,6
            if (ow == W - 1) inv |= 0x124;             // taps 2,5,8
            if (inv) {
#pragma unroll
                for (int t = 0; t < TAPS; t++)
                    if ((inv >> t) & 1) yv -= Ct[t];
            }

            yrow[(size_t)ol * COUT] = (short)yv;       // NHWC: coalesced over oc
            lsum += yv;
            lsq  += (long long)(yv * yv);
        }
    }

    atomicAdd(&g_sum[oc], lsum);
    atomicAdd(&g_sq[oc], (unsigned long long)lsq);
}

// ---------------- kernel 4: BN scale/shift from exact integer stats ----------------
__global__ void stats_kernel(const float* __restrict__ gamma,
                             const float* __restrict__ beta) {
    int c = threadIdx.x;
    const double cnt = (double)NHW;
    double mean = (double)g_sum[c] / cnt;
    double ex2  = (double)(long long)g_sq[c] / cnt;
    double var  = ex2 - mean * mean;
    double inv  = 1.0 / sqrt(var + 1e-5);
    double sc   = (double)gamma[c] * inv;
    g_scale[c] = (float)sc;
    g_shift[c] = (float)((double)beta[c] - mean * sc);
}

// ---------------- kernel 5: BN apply + NHWC -> NCHW ----------------
#define WT 28
__global__ void __launch_bounds__(256)
apply_kernel(float* __restrict__ out) {
    __shared__ float sy[WT * 257];                     // padded: conflict-free both phases
    const int wt = blockIdx.x, h = blockIdx.y, n = blockIdx.z;
    const int tid = threadIdx.x;

    for (int idx = tid; idx < WT * COUT; idx += 256) {
        int lw = idx >> 8;
        int oc = idx & 255;
        int gw = wt * WT + lw;
        float yv = (float)g_y[(((size_t)n * H + h) * W + gw) * COUT + oc];
        sy[lw * 257 + oc] = yv * g_scale[oc] + g_shift[oc];
    }
    __syncthreads();
    for (int idx = tid; idx < WT * COUT; idx += 256) {
        int oc = idx / WT;
        int lw = idx - oc * WT;
        out[(((size_t)n * COUT + oc) * H + h) * W + wt * WT + lw] = sy[lw * 257 + oc];
    }
}

// ---------------- launch ----------------
extern "C" void kernel_launch(void* const* d_in, const int* in_sizes, int n_in,
                              void* d_out, int out_size) {
    const float* x     = (const float*)d_in[0];
    const float* w     = (const float*)d_in[1];
    const float* gamma = (const float*)d_in[2];
    const float* beta  = (const float*)d_in[3];
    float* out = (float*)d_out;

    pack_x_kernel<<<(NHW + 255) / 256, 256>>>(x);
    pack_w_kernel<<<(COUT * TAPS * CW + 255) / 256, 256>>>(w);
    conv_kernel<<<CONV_CTAS, 256>>>();
    stats_kernel<<<1, COUT>>>(gamma, beta);
    apply_kernel<<<dim3(W / WT, H, NB), 256>>>(out);
}